// round 8
// baseline (speedup 1.0000x reference)
#include <cuda_runtime.h>
#include <cuda_bf16.h>

#define SS 1024
#define DD 512
#define HH 8
#define BBB 8
#define NQ (BBB*SS)
#define ND (NQ*DD)           // 4194304
#define WD (DD*DD)           // 262144
#define GP  72               // smem pitch in bf16 halves
#define GPB 144

// bf16 hi/lo planes (precomputed / produced by kernels)
__device__ __nv_bfloat16 g_inh[3*ND], g_inl[3*ND];   // query,key,value
__device__ __nv_bfloat16 g_wh[4*WD],  g_wl[4*WD];    // Wq,Wk,Wv,Wh
__device__ __nv_bfloat16 g_ph[3*ND],  g_pl[3*ND];    // projected Q,K,V
__device__ __nv_bfloat16 g_xh[ND],    g_xl[ND];      // attention output

// ---------------------------------------------------------------------------
__device__ __forceinline__ unsigned s2u(const void* p) {
    unsigned a;
    asm("{ .reg .u64 t; cvta.to.shared.u64 t, %1; cvt.u32.u64 %0, t; }" : "=r"(a) : "l"(p));
    return a;
}
__device__ __forceinline__ unsigned pack2bf(float x0, float x1) {
    unsigned r;
    asm("cvt.rn.bf16x2.f32 %0, %1, %2;" : "=r"(r) : "f"(x1), "f"(x0)); // low16=bf16(x0)
    return r;
}
__device__ __forceinline__ void mma_bf16(float c[4], unsigned a0, unsigned a1,
                                         unsigned a2, unsigned a3,
                                         unsigned b0, unsigned b1) {
    asm volatile("mma.sync.aligned.m16n8k16.row.col.f32.bf16.bf16.f32 "
        "{%0,%1,%2,%3}, {%4,%5,%6,%7}, {%8,%9}, {%0,%1,%2,%3};"
        : "+f"(c[0]), "+f"(c[1]), "+f"(c[2]), "+f"(c[3])
        : "r"(a0), "r"(a1), "r"(a2), "r"(a3), "r"(b0), "r"(b1));
}
__device__ __forceinline__ void ldm4(unsigned* r, unsigned addr) {
    asm volatile("ldmatrix.sync.aligned.m8n8.x4.shared.b16 {%0,%1,%2,%3}, [%4];"
        : "=r"(r[0]), "=r"(r[1]), "=r"(r[2]), "=r"(r[3]) : "r"(addr));
}
__device__ __forceinline__ void ldm4t(unsigned* r, unsigned addr) {
    asm volatile("ldmatrix.sync.aligned.m8n8.x4.trans.shared.b16 {%0,%1,%2,%3}, [%4];"
        : "=r"(r[0]), "=r"(r[1]), "=r"(r[2]), "=r"(r[3]) : "r"(addr));
}
__device__ __forceinline__ void cpa16(unsigned dst, const void* src) {
    asm volatile("cp.async.cg.shared.global [%0], [%1], 16;" :: "r"(dst), "l"(src));
}
#define CP_COMMIT() asm volatile("cp.async.commit_group;" ::: "memory")
#define CP_WAIT(n)  asm volatile("cp.async.wait_group %0;" :: "n"(n) : "memory")

// split f32x4 -> hi/lo bf16x2 pairs
__device__ __forceinline__ void split4(float4 v, uint2& hp, uint2& lp) {
    unsigned h0 = pack2bf(v.x, v.y), h1 = pack2bf(v.z, v.w);
    float a0 = __uint_as_float(h0 << 16), a1 = __uint_as_float(h0 & 0xFFFF0000u);
    float a2 = __uint_as_float(h1 << 16), a3 = __uint_as_float(h1 & 0xFFFF0000u);
    hp = make_uint2(h0, h1);
    lp = make_uint2(pack2bf(v.x - a0, v.y - a1), pack2bf(v.z - a2, v.w - a3));
}

// ===========================================================================
// f32 -> bf16 hi/lo planes
// ===========================================================================
__global__ __launch_bounds__(256) void cvt_hilo(
    const float* __restrict__ x, __nv_bfloat16* __restrict__ hp,
    __nv_bfloat16* __restrict__ lp, int n4)
{
    int i = blockIdx.x * 256 + threadIdx.x;
    if (i >= n4) return;
    uint2 h, l;
    split4(((const float4*)x)[i], h, l);
    ((uint2*)hp)[i] = h;
    ((uint2*)lp)[i] = l;
}

// ===========================================================================
// GEMM: C[8192,512] = A @ W^T. A,W given as bf16 hi/lo planes.
// CTA 128x64, warps 4(M)x2(N), k-chunks 64, cp.async double-buffered.
// Output: f32(+bias) if Cf, else bf16 hi/lo planes.
// ===========================================================================
#define GS_AH 0
#define GS_AL 18432
#define GS_WH 36864
#define GS_WL 46080
#define G_STAGE 55296
#define G_SM (2*G_STAGE)

__global__ __launch_bounds__(256) void gemm_mma(
    const __nv_bfloat16* __restrict__ Ah, const __nv_bfloat16* __restrict__ Al,
    const __nv_bfloat16* __restrict__ Wh, const __nv_bfloat16* __restrict__ Wl,
    const float* __restrict__ bias, float* __restrict__ Cf,
    __nv_bfloat16* __restrict__ Ch, __nv_bfloat16* __restrict__ Cl)
{
    extern __shared__ char sm[];
    const unsigned sb = s2u(sm);
    const int tid = threadIdx.x, lane = tid & 31, wid = tid >> 5;
    const int wm = wid & 3, wn = wid >> 2;
    const int g = lane >> 2, cq = lane & 3;
    const int m0 = blockIdx.y * 128, n0 = blockIdx.x * 64;

    const int aRow = lane & 15, aCol = (lane >> 4) << 3;
    const int bRow = (lane & 7) + ((lane >> 4) << 3), bCol = ((lane >> 3) & 1) << 3;
    const unsigned aH0 = sb + GS_AH + ((wm*32 + aRow)*GP + aCol)*2, dA = 16*GPB;
    const unsigned aL0 = sb + GS_AL + ((wm*32 + aRow)*GP + aCol)*2;
    const unsigned wH0 = sb + GS_WH + ((wn*32 + bRow)*GP + bCol)*2;
    const unsigned wL0 = sb + GS_WL + ((wn*32 + bRow)*GP + bCol)*2;

    const int rA = tid >> 3, oA = (tid & 7);          // A chunk coords (+128 rows per u)
    auto issue = [&](int kc, int st) {
        const unsigned s0 = sb + st * G_STAGE;
        const int k0 = kc * 64;
        #pragma unroll
        for (int u = 0; u < 4; ++u) {                 // A: 1024 chunks, 4/thread
            int c = tid + u * 256, row = c >> 3, off = c & 7;
            cpa16(s0 + GS_AH + row*GPB + off*16, Ah + (size_t)(m0 + row)*DD + k0 + off*8);
            cpa16(s0 + GS_AL + row*GPB + off*16, Al + (size_t)(m0 + row)*DD + k0 + off*8);
        }
        #pragma unroll
        for (int u = 0; u < 2; ++u) {                 // W: 512 chunks, 2/thread
            int c = tid + u * 256, row = c >> 3, off = c & 7;
            cpa16(s0 + GS_WH + row*GPB + off*16, Wh + (size_t)(n0 + row)*DD + k0 + off*8);
            cpa16(s0 + GS_WL + row*GPB + off*16, Wl + (size_t)(n0 + row)*DD + k0 + off*8);
        }
    };

    float acc[2][4][4] = {};
    issue(0, 0); CP_COMMIT();

    for (int kc = 0; kc < 8; ++kc) {
        if (kc < 7) { issue(kc + 1, (kc + 1) & 1); CP_COMMIT(); CP_WAIT(1); }
        else CP_WAIT(0);
        __syncthreads();
        const unsigned so = (unsigned)(kc & 1) * G_STAGE;
        #pragma unroll
        for (int kk = 0; kk < 4; ++kk) {
            const unsigned ko2 = so + kk * 32;
            unsigned ah[8], al[8], bh[8], bl[8];
            ldm4(ah,     aH0 + ko2); ldm4(ah + 4, aH0 + dA + ko2);
            ldm4(al,     aL0 + ko2); ldm4(al + 4, aL0 + dA + ko2);
            ldm4(bh,     wH0 + ko2); ldm4(bh + 4, wH0 + dA + ko2);
            ldm4(bl,     wL0 + ko2); ldm4(bl + 4, wL0 + dA + ko2);
            #pragma unroll
            for (int mt = 0; mt < 2; ++mt) {
                unsigned* ap = ah + mt * 4;
                unsigned* lp = al + mt * 4;
                #pragma unroll
                for (int nt = 0; nt < 4; ++nt) {
                    mma_bf16(acc[mt][nt], ap[0], ap[1], ap[2], ap[3], bh[2*nt], bh[2*nt+1]);
                    mma_bf16(acc[mt][nt], ap[0], ap[1], ap[2], ap[3], bl[2*nt], bl[2*nt+1]);
                    mma_bf16(acc[mt][nt], lp[0], lp[1], lp[2], lp[3], bh[2*nt], bh[2*nt+1]);
                }
            }
        }
        __syncthreads();
    }
    #pragma unroll
    for (int mt = 0; mt < 2; ++mt)
        #pragma unroll
        for (int nt = 0; nt < 4; ++nt) {
            int row = m0 + wm * 32 + mt * 16 + g;
            int col = n0 + wn * 32 + nt * 8 + 2 * cq;
            float v0 = acc[mt][nt][0], v1 = acc[mt][nt][1];
            float v2 = acc[mt][nt][2], v3 = acc[mt][nt][3];
            if (Cf) {
                float b0 = bias ? bias[col] : 0.f, b1 = bias ? bias[col + 1] : 0.f;
                *(float2*)(Cf + (size_t)row * DD + col)       = make_float2(v0 + b0, v1 + b1);
                *(float2*)(Cf + (size_t)(row + 8) * DD + col) = make_float2(v2 + b0, v3 + b1);
            } else {
                unsigned h0 = pack2bf(v0, v1), h1 = pack2bf(v2, v3);
                unsigned l0 = pack2bf(v0 - __uint_as_float(h0 << 16),
                                      v1 - __uint_as_float(h0 & 0xFFFF0000u));
                unsigned l1 = pack2bf(v2 - __uint_as_float(h1 << 16),
                                      v3 - __uint_as_float(h1 & 0xFFFF0000u));
                *(unsigned*)(Ch + (size_t)row * DD + col)       = h0;
                *(unsigned*)(Cl + (size_t)row * DD + col)       = l0;
                *(unsigned*)(Ch + (size_t)(row + 8) * DD + col) = h1;
                *(unsigned*)(Cl + (size_t)(row + 8) * DD + col) = l1;
            }
        }
}

// ===========================================================================
// Attention: CTA=(h, qtile 64, b). Q/K/V as hi/lo planes, cp.async 2-stage.
// ===========================================================================
#define AS_KH 0
#define AS_KL 9216
#define AS_VH 18432
#define AS_VL 27648
#define A_STAGE 36864
#define A_ST0 18432          // Q planes occupy [0, 18432)
#define A_LS (A_ST0 + 2*A_STAGE)   // 92160
#define A_LI (A_LS + 512)
#define A_SM (A_LI + 512)
#define OPITCH 68

__global__ __launch_bounds__(256) void attn_mma(
    const __nv_bfloat16* __restrict__ Qh, const __nv_bfloat16* __restrict__ Ql,
    const __nv_bfloat16* __restrict__ Kh, const __nv_bfloat16* __restrict__ Kl,
    const __nv_bfloat16* __restrict__ Vh, const __nv_bfloat16* __restrict__ Vl,
    const float* __restrict__ gprob, const int* __restrict__ mask,
    __nv_bfloat16* __restrict__ Xh, __nv_bfloat16* __restrict__ Xl)
{
    extern __shared__ char sm[];
    const unsigned sb = s2u(sm);
    float* LSM = (float*)(sm + A_LS);
    float* LIS = (float*)(sm + A_LI);
    float* OSM = (float*)(sm + A_ST0);         // reused after mainloop

    const int tid = threadIdx.x, lane = tid & 31, wid = tid >> 5;
    const int wm = wid & 3, wn = wid >> 2;
    const int g = lane >> 2, cq = lane & 3;
    const int h = blockIdx.x, qt = blockIdx.y, b = blockIdx.z;
    const int q0 = qt * 64;

    const int aRow = lane & 15, aCol = (lane >> 4) << 3;
    const int bRow = (lane & 7) + ((lane >> 4) << 3), bCol = ((lane >> 3) & 1) << 3;
    const unsigned qHa = sb + ((wm*16 + aRow)*GP + aCol)*2;
    const unsigned qLa = qHa + 9216;
    const unsigned kH0 = sb + A_ST0 + AS_KH + ((wn*32 + bRow)*GP + bCol)*2, dK = 16*GPB;
    const unsigned kL0 = kH0 + 9216;
    const unsigned vHa = sb + A_ST0 + AS_VH + ((wn*32 + aRow)*GP + aCol)*2;
    const unsigned vLa = vHa + 9216;

    const size_t hb = (size_t)b * SS * DD + h * 64;

    auto issueKV = [&](int kt, int st) {
        const unsigned s0 = sb + A_ST0 + st * A_STAGE;
        const int k0 = kt * 64;
        #pragma unroll
        for (int u = 0; u < 2; ++u) {
            int c = tid + u * 256, row = c >> 3, off = c & 7;
            const size_t gsrc = hb + (size_t)(k0 + row) * DD + off * 8;
            cpa16(s0 + AS_KH + row*GPB + off*16, Kh + gsrc);
            cpa16(s0 + AS_KL + row*GPB + off*16, Kl + gsrc);
            cpa16(s0 + AS_VH + row*GPB + off*16, Vh + gsrc);
            cpa16(s0 + AS_VL + row*GPB + off*16, Vl + gsrc);
        }
    };
    // Q tile (group 0, once)
    #pragma unroll
    for (int u = 0; u < 2; ++u) {
        int c = tid + u * 256, row = c >> 3, off = c & 7;
        const size_t gsrc = hb + (size_t)(q0 + row) * DD + off * 8;
        cpa16(sb + row*GPB + off*16,        Qh + gsrc);
        cpa16(sb + 9216 + row*GPB + off*16, Ql + gsrc);
    }
    issueKV(0, 0); CP_COMMIT();

    const int qg0 = q0 + wm * 16 + g, qg1 = qg0 + 8;
    const int*   mr0 = mask  + ((size_t)b * SS + qg0) * SS;
    const int*   mr1 = mask  + ((size_t)b * SS + qg1) * SS;
    const float* gr0 = gprob + ((size_t)b * SS + qg0) * SS;
    const float* gr1 = gprob + ((size_t)b * SS + qg1) * SS;

    float o[8][4] = {};
    float lsum0 = 0.f, lsum1 = 0.f;

    for (int kt = 0; kt < 16; ++kt) {
        if (kt < 15) { issueKV(kt + 1, (kt + 1) & 1); CP_COMMIT(); CP_WAIT(1); }
        else CP_WAIT(0);
        __syncthreads();
        const unsigned so = (unsigned)(kt & 1) * A_STAGE;
        const int k0 = kt * 64;

        // ---- S = Q.K^T ----
        float s[4][4] = {};
        #pragma unroll
        for (int kk = 0; kk < 4; ++kk) {
            const unsigned ko2 = kk * 32;
            unsigned aH[4], aL[4], bh[8], bl[8];
            ldm4(aH, qHa + ko2);
            ldm4(aL, qLa + ko2);
            ldm4(bh,     kH0 + so + ko2); ldm4(bh + 4, kH0 + so + dK + ko2);
            ldm4(bl,     kL0 + so + ko2); ldm4(bl + 4, kL0 + so + dK + ko2);
            #pragma unroll
            for (int nt = 0; nt < 4; ++nt) {
                mma_bf16(s[nt], aH[0], aH[1], aH[2], aH[3], bh[2*nt], bh[2*nt+1]);
                mma_bf16(s[nt], aH[0], aH[1], aH[2], aH[3], bl[2*nt], bl[2*nt+1]);
                mma_bf16(s[nt], aL[0], aL[1], aL[2], aL[3], bh[2*nt], bh[2*nt+1]);
            }
        }

        // ---- softmax numerator (no max-sub; masked -> exact 0) ----
        unsigned PHf[4][2], PLf[4][2];
        #pragma unroll
        for (int nt = 0; nt < 4; ++nt) {
            const int kg = k0 + wn * 32 + nt * 8 + 2 * cq;
            int2   m0v = *(const int2*)(mr0 + kg);
            int2   m1v = *(const int2*)(mr1 + kg);
            float2 g0v = *(const float2*)(gr0 + kg);
            float2 g1v = *(const float2*)(gr1 + kg);
            float p00 = (m0v.x | (int)(kg     == qg0)) ? __expf(s[nt][0] * 0.125f) : 0.f;
            float p01 = (m0v.y | (int)(kg + 1 == qg0)) ? __expf(s[nt][1] * 0.125f) : 0.f;
            float p10 = (m1v.x | (int)(kg     == qg1)) ? __expf(s[nt][2] * 0.125f) : 0.f;
            float p11 = (m1v.y | (int)(kg + 1 == qg1)) ? __expf(s[nt][3] * 0.125f) : 0.f;
            lsum0 += p00 + p01;
            lsum1 += p10 + p11;
            float t00 = p00 * g0v.x, t01 = p01 * g0v.y;
            float t10 = p10 * g1v.x, t11 = p11 * g1v.y;
            unsigned h0 = pack2bf(t00, t01), h1 = pack2bf(t10, t11);
            PHf[nt][0] = h0; PHf[nt][1] = h1;
            PLf[nt][0] = pack2bf(t00 - __uint_as_float(h0 << 16),
                                 t01 - __uint_as_float(h0 & 0xFFFF0000u));
            PLf[nt][1] = pack2bf(t10 - __uint_as_float(h1 << 16),
                                 t11 - __uint_as_float(h1 & 0xFFFF0000u));
        }

        // ---- O += P.V (ldmatrix.trans on natural-layout V) ----
        #pragma unroll
        for (int kk2 = 0; kk2 < 2; ++kk2) {
            const unsigned kofs = so + (unsigned)kk2 * 16 * GPB;
            unsigned vh[16], vl[16];
            #pragma unroll
            for (int dq = 0; dq < 4; ++dq) {
                ldm4t(vh + dq * 4, vHa + kofs + dq * 32);
                ldm4t(vl + dq * 4, vLa + kofs + dq * 32);
            }
            unsigned ph0 = PHf[2*kk2][0], ph1 = PHf[2*kk2][1];
            unsigned ph2 = PHf[2*kk2+1][0], ph3 = PHf[2*kk2+1][1];
            unsigned pl0 = PLf[2*kk2][0], pl1 = PLf[2*kk2][1];
            unsigned pl2 = PLf[2*kk2+1][0], pl3 = PLf[2*kk2+1][1];
            #pragma unroll
            for (int dn = 0; dn < 8; ++dn) {
                mma_bf16(o[dn], ph0, ph1, ph2, ph3, vh[2*dn], vh[2*dn+1]);
                mma_bf16(o[dn], ph0, ph1, ph2, ph3, vl[2*dn], vl[2*dn+1]);
                mma_bf16(o[dn], pl0, pl1, pl2, pl3, vh[2*dn], vh[2*dn+1]);
            }
        }
        __syncthreads();
    }

    // ---- epilogue ----
    lsum0 += __shfl_xor_sync(0xFFFFFFFFu, lsum0, 1);
    lsum0 += __shfl_xor_sync(0xFFFFFFFFu, lsum0, 2);
    lsum1 += __shfl_xor_sync(0xFFFFFFFFu, lsum1, 1);
    lsum1 += __shfl_xor_sync(0xFFFFFFFFu, lsum1, 2);
    if (cq == 0) {
        LSM[wn * 64 + wm * 16 + g]     = lsum0;
        LSM[wn * 64 + wm * 16 + g + 8] = lsum1;
    }
    __syncthreads();
    if (tid < 64) LIS[tid] = 1.0f / (LSM[tid] + LSM[64 + tid]);
    if (wn == 0) {
        #pragma unroll
        for (int dn = 0; dn < 8; ++dn) {
            int r0 = wm * 16 + g, col = dn * 8 + 2 * cq;
            *(float2*)(OSM + r0 * OPITCH + col)       = make_float2(o[dn][0], o[dn][1]);
            *(float2*)(OSM + (r0 + 8) * OPITCH + col) = make_float2(o[dn][2], o[dn][3]);
        }
    }
    __syncthreads();
    if (wn == 1) {
        #pragma unroll
        for (int dn = 0; dn < 8; ++dn) {
            int r0 = wm * 16 + g, col = dn * 8 + 2 * cq;
            float2* p0 = (float2*)(OSM + r0 * OPITCH + col);
            float2* p1 = (float2*)(OSM + (r0 + 8) * OPITCH + col);
            p0->x += o[dn][0]; p0->y += o[dn][1];
            p1->x += o[dn][2]; p1->y += o[dn][3];
        }
    }
    __syncthreads();
    #pragma unroll
    for (int u = 0; u < 4; ++u) {
        int idx = tid + u * 256, rr = idx >> 4, c4 = idx & 15;
        float li = LIS[rr];
        float4 vv = *(float4*)(OSM + rr * OPITCH + c4 * 4);
        vv.x *= li; vv.y *= li; vv.z *= li; vv.w *= li;
        uint2 hp, lp;
        split4(vv, hp, lp);
        size_t oi = hb + (size_t)(q0 + rr) * DD + c4 * 4;
        *(uint2*)(Xh + oi) = hp;
        *(uint2*)(Xl + oi) = lp;
    }
}

// ===========================================================================
extern "C" void kernel_launch(void* const* d_in, const int* in_sizes, int n_in,
                              void* d_out, int out_size)
{
    const float* query = (const float*)d_in[0];
    const float* key   = (const float*)d_in[1];
    const float* value = (const float*)d_in[2];
    const float* gprob = (const float*)d_in[3];
    const float* Wq    = (const float*)d_in[4];
    const float* Wk    = (const float*)d_in[5];
    const float* Wv    = (const float*)d_in[6];
    const float* Wv2   = (const float*)d_in[7];   // Wh
    const float* bh    = (const float*)d_in[8];
    const int*   mask  = (const int*)d_in[9];
    float* out = (float*)d_out;

    __nv_bfloat16 *inh, *inl, *wh, *wl, *ph, *pl, *xh, *xl;
    cudaGetSymbolAddress((void**)&inh, g_inh);
    cudaGetSymbolAddress((void**)&inl, g_inl);
    cudaGetSymbolAddress((void**)&wh,  g_wh);
    cudaGetSymbolAddress((void**)&wl,  g_wl);
    cudaGetSymbolAddress((void**)&ph,  g_ph);
    cudaGetSymbolAddress((void**)&pl,  g_pl);
    cudaGetSymbolAddress((void**)&xh,  g_xh);
    cudaGetSymbolAddress((void**)&xl,  g_xl);

    cudaFuncSetAttribute(gemm_mma, cudaFuncAttributeMaxDynamicSharedMemorySize, G_SM);
    cudaFuncSetAttribute(attn_mma, cudaFuncAttributeMaxDynamicSharedMemorySize, A_SM);

    // conversions
    cvt_hilo<<<ND/4/256, 256>>>(query, inh,        inl,        ND/4);
    cvt_hilo<<<ND/4/256, 256>>>(key,   inh + ND,   inl + ND,   ND/4);
    cvt_hilo<<<ND/4/256, 256>>>(value, inh + 2*ND, inl + 2*ND, ND/4);
    cvt_hilo<<<WD/4/256, 256>>>(Wq,  wh,        wl,        WD/4);
    cvt_hilo<<<WD/4/256, 256>>>(Wk,  wh + WD,   wl + WD,   WD/4);
    cvt_hilo<<<WD/4/256, 256>>>(Wv,  wh + 2*WD, wl + 2*WD, WD/4);
    cvt_hilo<<<WD/4/256, 256>>>(Wv2, wh + 3*WD, wl + 3*WD, WD/4);

    dim3 blk(256);
    dim3 pg(DD / 64, NQ / 128);                 // (8, 64)
    gemm_mma<<<pg, blk, G_SM>>>(inh,        inl,        wh,        wl,        nullptr, nullptr, ph,        pl);
    gemm_mma<<<pg, blk, G_SM>>>(inh + ND,   inl + ND,   wh + WD,   wl + WD,   nullptr, nullptr, ph + ND,   pl + ND);
    gemm_mma<<<pg, blk, G_SM>>>(inh + 2*ND, inl + 2*ND, wh + 2*WD, wl + 2*WD, nullptr, nullptr, ph + 2*ND, pl + 2*ND);

    attn_mma<<<dim3(HH, SS / 64, BBB), blk, A_SM>>>(ph, pl, ph + ND, pl + ND,
                                                    ph + 2*ND, pl + 2*ND,
                                                    gprob, mask, xh, xl);

    gemm_mma<<<pg, blk, G_SM>>>(xh, xl, wh + 3*WD, wl + 3*WD, bh, out, nullptr, nullptr);
}

// round 9
// speedup vs baseline: 1.4017x; 1.4017x over previous
#include <cuda_runtime.h>
#include <cuda_fp16.h>

#define SS 1024
#define DD 512
#define HH 8
#define BBB 8
#define NQ (BBB*SS)
#define GP  72        // smem pitch in fp16 halves (144B rows -> conflict-free ldmatrix)
#define GPB 144

__device__ float g_Q[NQ*DD];
__device__ float g_K[NQ*DD];
__device__ float g_V[NQ*DD];
__device__ float g_X[NQ*DD];

// ---------------------------------------------------------------------------
__device__ __forceinline__ unsigned s2u(const void* p) {
    unsigned a;
    asm("{ .reg .u64 t; cvta.to.shared.u64 t, %1; cvt.u32.u64 %0, t; }" : "=r"(a) : "l"(p));
    return a;
}
__device__ __forceinline__ unsigned pack2h(float x0, float x1) {
    unsigned r;
    asm("cvt.rn.f16x2.f32 %0, %1, %2;" : "=r"(r) : "f"(x1), "f"(x0)); // low16=f16(x0)
    return r;
}
__device__ __forceinline__ void mma_f16(float c[4], unsigned a0, unsigned a1,
                                        unsigned a2, unsigned a3,
                                        unsigned b0, unsigned b1) {
    asm volatile("mma.sync.aligned.m16n8k16.row.col.f32.f16.f16.f32 "
        "{%0,%1,%2,%3}, {%4,%5,%6,%7}, {%8,%9}, {%0,%1,%2,%3};"
        : "+f"(c[0]), "+f"(c[1]), "+f"(c[2]), "+f"(c[3])
        : "r"(a0), "r"(a1), "r"(a2), "r"(a3), "r"(b0), "r"(b1));
}
__device__ __forceinline__ void ldm4(unsigned* r, unsigned addr) {
    asm volatile("ldmatrix.sync.aligned.m8n8.x4.shared.b16 {%0,%1,%2,%3}, [%4];"
        : "=r"(r[0]), "=r"(r[1]), "=r"(r[2]), "=r"(r[3]) : "r"(addr));
}
__device__ __forceinline__ void ldm4t(unsigned* r, unsigned addr) {
    asm volatile("ldmatrix.sync.aligned.m8n8.x4.trans.shared.b16 {%0,%1,%2,%3}, [%4];"
        : "=r"(r[0]), "=r"(r[1]), "=r"(r[2]), "=r"(r[3]) : "r"(addr));
}
// f32x4 -> fp16x4, one 8B store at [r][cbyte], pitch GPB
__device__ __forceinline__ void sts_h(char* base, int r, int cbyte, float4 v) {
    *(uint2*)(base + r*GPB + cbyte) = make_uint2(pack2h(v.x, v.y), pack2h(v.z, v.w));
}

// ===========================================================================
// GEMM: C[8192,512] = A[8192,512] @ W[512,512]^T (+bias)
// CTA 128x64, 8 warps 4(M)x2(N), warp tile 32x32, k-chunks of 64, fp16 single.
// ===========================================================================
#define G_AH 0
#define G_WH 18432
#define G_SM 27648

__global__ __launch_bounds__(256) void gemm_mma(
    const float* __restrict__ A, const float* __restrict__ W,
    const float* __restrict__ bias, float* __restrict__ C)
{
    extern __shared__ char sm[];
    char* AH = sm + G_AH;
    char* WH = sm + G_WH;
    const unsigned sb = s2u(sm);
    const int tid = threadIdx.x, lane = tid & 31, wid = tid >> 5;
    const int wm = wid & 3, wn = wid >> 2;
    const int g = lane >> 2, cq = lane & 3;
    const int m0 = blockIdx.y * 128, n0 = blockIdx.x * 64;

    const int aRow = lane & 15, aCol = (lane >> 4) << 3;
    const int bRow = (lane & 7) + ((lane >> 4) << 3), bCol = ((lane >> 3) & 1) << 3;
    const unsigned aH0 = sb + G_AH + ((wm*32 + aRow)*GP + aCol)*2, dA = 16*GPB;
    const unsigned wH0 = sb + G_WH + ((wn*32 + bRow)*GP + bCol)*2;

    float acc[2][4][4] = {};

    for (int kc = 0; kc < 8; ++kc) {
        const int k0 = kc * 64;
        #pragma unroll
        for (int u = 0; u < 8; ++u) {               // A tile 128x64 f32
            int idx = tid + u * 256, rr = idx >> 4, c4 = idx & 15;
            float4 v = *(const float4*)(A + (size_t)(m0 + rr) * DD + k0 + c4 * 4);
            sts_h(AH, rr, c4 * 8, v);
        }
        #pragma unroll
        for (int u = 0; u < 4; ++u) {               // W tile 64x64 f32
            int idx = tid + u * 256, rr = idx >> 4, c4 = idx & 15;
            float4 v = *(const float4*)(W + (size_t)(n0 + rr) * DD + k0 + c4 * 4);
            sts_h(WH, rr, c4 * 8, v);
        }
        __syncthreads();
        #pragma unroll
        for (int kk = 0; kk < 4; ++kk) {
            const unsigned ko2 = kk * 32;
            unsigned a[8], b[8];
            ldm4(a,     aH0 + ko2); ldm4(a + 4, aH0 + dA + ko2);
            ldm4(b,     wH0 + ko2); ldm4(b + 4, wH0 + dA + ko2);
            #pragma unroll
            for (int mt = 0; mt < 2; ++mt) {
                unsigned* ap = a + mt * 4;
                #pragma unroll
                for (int nt = 0; nt < 4; ++nt)
                    mma_f16(acc[mt][nt], ap[0], ap[1], ap[2], ap[3], b[2*nt], b[2*nt+1]);
            }
        }
        __syncthreads();
    }
    #pragma unroll
    for (int mt = 0; mt < 2; ++mt)
        #pragma unroll
        for (int nt = 0; nt < 4; ++nt) {
            int row = m0 + wm * 32 + mt * 16 + g;
            int col = n0 + wn * 32 + nt * 8 + 2 * cq;
            float b0 = bias ? bias[col] : 0.f, b1 = bias ? bias[col + 1] : 0.f;
            *(float2*)(C + (size_t)row * DD + col) =
                make_float2(acc[mt][nt][0] + b0, acc[mt][nt][1] + b1);
            *(float2*)(C + (size_t)(row + 8) * DD + col) =
                make_float2(acc[mt][nt][2] + b0, acc[mt][nt][3] + b1);
        }
}

// ===========================================================================
// Attention: CTA=(h, qtile 64, b). Flash, no-max softmax, fp16 single.
// V kept NATURAL [k][d] in smem; P.V B-frags via ldmatrix.trans.
// ===========================================================================
#define A_QH 0
#define A_KH 9216
#define A_VH 18432
#define A_LS 27648
#define A_LI 28160
#define A_SM 28416
#define OPITCH 68

__global__ __launch_bounds__(256) void attn_mma(
    const float* __restrict__ Q, const float* __restrict__ K,
    const float* __restrict__ V, const float* __restrict__ gprob,
    const int* __restrict__ mask, float* __restrict__ X)
{
    extern __shared__ char sm[];
    char* QH = sm + A_QH;
    char* KH = sm + A_KH;
    char* VH = sm + A_VH;
    float* LSM = (float*)(sm + A_LS);
    float* LIS = (float*)(sm + A_LI);
    float* OSM = (float*)(sm + A_KH);          // reused after mainloop
    const unsigned sb = s2u(sm);

    const int tid = threadIdx.x, lane = tid & 31, wid = tid >> 5;
    const int wm = wid & 3, wn = wid >> 2;
    const int g = lane >> 2, cq = lane & 3;
    const int h = blockIdx.x, qt = blockIdx.y, b = blockIdx.z;
    const int q0 = qt * 64;

    const int aRow = lane & 15, aCol = (lane >> 4) << 3;
    const int bRow = (lane & 7) + ((lane >> 4) << 3), bCol = ((lane >> 3) & 1) << 3;
    const unsigned qHa = sb + A_QH + ((wm*16 + aRow)*GP + aCol)*2;
    const unsigned kH0 = sb + A_KH + ((wn*32 + bRow)*GP + bCol)*2, dK = 16*GPB;
    const unsigned vHa = sb + A_VH + ((wn*32 + aRow)*GP + aCol)*2; // rows = k

    const float* Qb = Q + (size_t)b * SS * DD + h * 64;
    const float* Kb = K + (size_t)b * SS * DD + h * 64;
    const float* Vb = V + (size_t)b * SS * DD + h * 64;

    #pragma unroll
    for (int u = 0; u < 4; ++u) {               // Q tile 64x64
        int idx = tid + u * 256, rr = idx >> 4, c4 = idx & 15;
        float4 v = *(const float4*)(Qb + (size_t)(q0 + rr) * DD + c4 * 4);
        sts_h(QH, rr, c4 * 8, v);
    }

    const int qg0 = q0 + wm * 16 + g, qg1 = qg0 + 8;
    const int*   mr0 = mask  + ((size_t)b * SS + qg0) * SS;
    const int*   mr1 = mask  + ((size_t)b * SS + qg1) * SS;
    const float* gr0 = gprob + ((size_t)b * SS + qg0) * SS;
    const float* gr1 = gprob + ((size_t)b * SS + qg1) * SS;

    float o[8][4] = {};
    float lsum0 = 0.f, lsum1 = 0.f;
    __syncthreads();

    for (int kt = 0; kt < 16; ++kt) {
        const int k0 = kt * 64;
        #pragma unroll
        for (int u = 0; u < 4; ++u) {           // K tile 64x64 [kpos][dk]
            int idx = tid + u * 256, rr = idx >> 4, c4 = idx & 15;
            float4 v = *(const float4*)(Kb + (size_t)(k0 + rr) * DD + c4 * 4);
            sts_h(KH, rr, c4 * 8, v);
        }
        #pragma unroll
        for (int u = 0; u < 4; ++u) {           // V tile 64x64 NATURAL [kpos][d]
            int idx = tid + u * 256, rr = idx >> 4, c4 = idx & 15;
            float4 v = *(const float4*)(Vb + (size_t)(k0 + rr) * DD + c4 * 4);
            sts_h(VH, rr, c4 * 8, v);
        }
        __syncthreads();

        // ---- S = Q.K^T (warp tile 16x32) ----
        float s[4][4] = {};
        #pragma unroll
        for (int kk = 0; kk < 4; ++kk) {
            const unsigned ko2 = kk * 32;
            unsigned aH[4], bh[8];
            ldm4(aH, qHa + ko2);
            ldm4(bh,     kH0 + ko2); ldm4(bh + 4, kH0 + dK + ko2);
            #pragma unroll
            for (int nt = 0; nt < 4; ++nt)
                mma_f16(s[nt], aH[0], aH[1], aH[2], aH[3], bh[2*nt], bh[2*nt+1]);
        }

        // ---- softmax numerator (no max-sub; masked -> exact 0); pack P fp16 ----
        unsigned PHf[4][2];
        #pragma unroll
        for (int nt = 0; nt < 4; ++nt) {
            const int kg = k0 + wn * 32 + nt * 8 + 2 * cq;
            int2   m0v = *(const int2*)(mr0 + kg);
            int2   m1v = *(const int2*)(mr1 + kg);
            float2 g0v = *(const float2*)(gr0 + kg);
            float2 g1v = *(const float2*)(gr1 + kg);
            float p00 = (m0v.x | (int)(kg     == qg0)) ? __expf(s[nt][0] * 0.125f) : 0.f;
            float p01 = (m0v.y | (int)(kg + 1 == qg0)) ? __expf(s[nt][1] * 0.125f) : 0.f;
            float p10 = (m1v.x | (int)(kg     == qg1)) ? __expf(s[nt][2] * 0.125f) : 0.f;
            float p11 = (m1v.y | (int)(kg + 1 == qg1)) ? __expf(s[nt][3] * 0.125f) : 0.f;
            lsum0 += p00 + p01;
            lsum1 += p10 + p11;
            PHf[nt][0] = pack2h(p00 * g0v.x, p01 * g0v.y);
            PHf[nt][1] = pack2h(p10 * g1v.x, p11 * g1v.y);
        }

        // ---- O_partial += P.V ; V B-frags via ldmatrix.trans ----
        #pragma unroll
        for (int kk2 = 0; kk2 < 2; ++kk2) {
            const unsigned kofs = (unsigned)kk2 * 16 * GPB;
            unsigned vh[16];
            #pragma unroll
            for (int dq = 0; dq < 4; ++dq)
                ldm4t(vh + dq * 4, vHa + kofs + dq * 32);
            unsigned p0 = PHf[2*kk2][0], p1 = PHf[2*kk2][1];
            unsigned p2 = PHf[2*kk2+1][0], p3 = PHf[2*kk2+1][1];
            #pragma unroll
            for (int dn = 0; dn < 8; ++dn)
                mma_f16(o[dn], p0, p1, p2, p3, vh[2*dn], vh[2*dn+1]);
        }
        __syncthreads();
    }

    // ---- epilogue: l reduce, O combine across wn, write out ----
    lsum0 += __shfl_xor_sync(0xFFFFFFFFu, lsum0, 1);
    lsum0 += __shfl_xor_sync(0xFFFFFFFFu, lsum0, 2);
    lsum1 += __shfl_xor_sync(0xFFFFFFFFu, lsum1, 1);
    lsum1 += __shfl_xor_sync(0xFFFFFFFFu, lsum1, 2);
    if (cq == 0) {
        LSM[wn * 64 + wm * 16 + g]     = lsum0;
        LSM[wn * 64 + wm * 16 + g + 8] = lsum1;
    }
    __syncthreads();
    if (tid < 64) LIS[tid] = 1.0f / (LSM[tid] + LSM[64 + tid]);
    if (wn == 0) {
        #pragma unroll
        for (int dn = 0; dn < 8; ++dn) {
            int r0 = wm * 16 + g, col = dn * 8 + 2 * cq;
            *(float2*)(OSM + r0 * OPITCH + col)       = make_float2(o[dn][0], o[dn][1]);
            *(float2*)(OSM + (r0 + 8) * OPITCH + col) = make_float2(o[dn][2], o[dn][3]);
        }
    }
    __syncthreads();
    if (wn == 1) {
        #pragma unroll
        for (int dn = 0; dn < 8; ++dn) {
            int r0 = wm * 16 + g, col = dn * 8 + 2 * cq;
            float2* p0 = (float2*)(OSM + r0 * OPITCH + col);
            float2* p1 = (float2*)(OSM + (r0 + 8) * OPITCH + col);
            p0->x += o[dn][0]; p0->y += o[dn][1];
            p1->x += o[dn][2]; p1->y += o[dn][3];
        }
    }
    __syncthreads();
    #pragma unroll
    for (int u = 0; u < 4; ++u) {
        int idx = tid + u * 256, rr = idx >> 4, c4 = idx & 15;
        float li = LIS[rr];
        float4 vv = *(float4*)(OSM + rr * OPITCH + c4 * 4);
        vv.x *= li; vv.y *= li; vv.z *= li; vv.w *= li;
        *(float4*)(X + ((size_t)b * SS + q0 + rr) * DD + h * 64 + c4 * 4) = vv;
    }
}

// ===========================================================================
extern "C" void kernel_launch(void* const* d_in, const int* in_sizes, int n_in,
                              void* d_out, int out_size)
{
    const float* query = (const float*)d_in[0];
    const float* key   = (const float*)d_in[1];
    const float* value = (const float*)d_in[2];
    const float* gprob = (const float*)d_in[3];
    const float* Wq    = (const float*)d_in[4];
    const float* Wk    = (const float*)d_in[5];
    const float* Wv    = (const float*)d_in[6];
    const float* Wh    = (const float*)d_in[7];
    const float* bh    = (const float*)d_in[8];
    const int*   mask  = (const int*)d_in[9];
    float* out = (float*)d_out;

    float *Qp, *Kp, *Vp, *Xp;
    cudaGetSymbolAddress((void**)&Qp, g_Q);
    cudaGetSymbolAddress((void**)&Kp, g_K);
    cudaGetSymbolAddress((void**)&Vp, g_V);
    cudaGetSymbolAddress((void**)&Xp, g_X);

    cudaFuncSetAttribute(gemm_mma, cudaFuncAttributeMaxDynamicSharedMemorySize, G_SM);
    cudaFuncSetAttribute(attn_mma, cudaFuncAttributeMaxDynamicSharedMemorySize, A_SM);

    dim3 blk(256);
    dim3 pg(DD / 64, NQ / 128);                 // (8, 64)
    gemm_mma<<<pg, blk, G_SM>>>(query, Wq, nullptr, Qp);
    gemm_mma<<<pg, blk, G_SM>>>(key,   Wk, nullptr, Kp);
    gemm_mma<<<pg, blk, G_SM>>>(value, Wv, nullptr, Vp);
    attn_mma<<<dim3(HH, SS / 64, BBB), blk, A_SM>>>(Qp, Kp, Vp, gprob, mask, Xp);
    gemm_mma<<<pg, blk, G_SM>>>(Xp, Wh, bh, out);
}